// round 5
// baseline (speedup 1.0000x reference)
#include <cuda_runtime.h>
#include <cstdint>

// ---------------------------------------------------------------------------
// GAT (3 layers, single head) on GB300.
//  0: x [N, F_IN] f32
//  1: edge_index [2, E] int (dtype detected at runtime: int32 vs int64)
//  2..5:  W1 [F_IN,64], a_src1[64], a_dst1[64], b1[64]
//  6..9:  W2 [64,64],   a_src2,    a_dst2,    b2
// 10..13: W3 [64,64],   a_src3,    a_dst3,    b3
// output: [N, 64] f32
// ---------------------------------------------------------------------------

#define HID 64
#define NMAX 131072
#define EMAX 3400000

__device__ __align__(16) int      g_src[EMAX];
__device__ __align__(16) int      g_dst[EMAX];
__device__ __align__(16) float    g_ew[EMAX];                  // e, then exp(e-m)
__device__ __align__(16) float    g_H[(size_t)NMAX * HID];     // post-GEMM hidden
__device__ __align__(16) float    g_O[(size_t)NMAX * HID];     // aggregated output
__device__ __align__(16) float    g_es[NMAX];
__device__ __align__(16) float    g_ed[NMAX];
__device__ __align__(16) float    g_selfe[NMAX];
__device__ __align__(16) float    g_m[NMAX];
__device__ __align__(16) float    g_s[NMAX];
__device__ __align__(16) unsigned g_menc[NMAX];
__device__ int g_is32;

// monotone float<->uint encoding for atomicMax on floats (handles negatives)
__device__ __forceinline__ unsigned encf(float f) {
    unsigned u = __float_as_uint(f);
    return (u & 0x80000000u) ? ~u : (u | 0x80000000u);
}
__device__ __forceinline__ float decf(unsigned u) {
    return __uint_as_float((u & 0x80000000u) ? (u & 0x7fffffffu) : ~u);
}

__device__ __forceinline__ float leaky(float v) { return v > 0.f ? v : 0.2f * v; }

// ---------------------------------------------------------------------------
// dtype detection: if the buffer is really int64, every value < N (=1e5).
// If it's int32 read as int64, most words pack two ids -> value >= 2^32.
// ---------------------------------------------------------------------------
__global__ void detect_dtype(const unsigned long long* __restrict__ ei, int nscan) {
    __shared__ int flag;
    if (threadIdx.x == 0) flag = 0;
    __syncthreads();
    for (int j = threadIdx.x; j < nscan; j += blockDim.x)
        if (ei[j] >= 0x100000000ull) flag = 1;
    __syncthreads();
    if (threadIdx.x == 0) g_is32 = flag;
}

// ---------------------------------------------------------------------------
// edge index conversion (once, reused by all 3 layers); clamps to [0,N)
// ---------------------------------------------------------------------------
__global__ void conv_idx(const void* __restrict__ eiv, int E, int N) {
    int i = blockIdx.x * blockDim.x + threadIdx.x;
    if (i >= E) return;
    int s, d;
    if (g_is32) {
        const int* p = (const int*)eiv;
        s = p[i]; d = p[(size_t)E + i];
    } else {
        const long long* p = (const long long*)eiv;
        s = (int)p[i]; d = (int)p[(size_t)E + i];
    }
    // defensive clamp: never let a bad index fault the whole run
    s = min(max(s, 0), N - 1);
    d = min(max(d, 0), N - 1);
    g_src[i] = s;
    g_dst[i] = d;
}

// ---------------------------------------------------------------------------
// GEMM: g_H[M,64] = act(X[M,K]) @ W[K,64].  K in {64,128}.
// 64x64 block tile, 256 threads, 4x4 register tile per thread.
// FROM_GO: read input rows from g_O instead of X param.
// ---------------------------------------------------------------------------
template<bool RELU, bool FROM_GO>
__global__ void __launch_bounds__(256)
gemm_k(const float* __restrict__ X, const float* __restrict__ W, int M, int K) {
    __shared__ float Ws[64 * 64];
    __shared__ float Xs[64 * 68];  // stride 68 to dodge bank conflicts

    const int tid = threadIdx.x;
    const int tx = tid & 15;        // 16 col-groups of 4 cols
    const int ty = tid >> 4;        // 16 row-groups of 4 rows
    const int row0 = blockIdx.x << 6;

    const float* __restrict__ Xp = FROM_GO ? g_O : X;

    float acc[4][4];
#pragma unroll
    for (int r = 0; r < 4; r++)
#pragma unroll
        for (int c = 0; c < 4; c++) acc[r][c] = 0.f;

    for (int kk = 0; kk < K; kk += 64) {
#pragma unroll
        for (int p = 0; p < 4; p++) {
            int r = ty + (p << 4);          // 0..63
            int c = tx << 2;                // 0..60
            *(float4*)&Ws[r * 64 + c] = *(const float4*)&W[(size_t)(kk + r) * HID + c];
            int grow = row0 + r;
            float4 v = make_float4(0.f, 0.f, 0.f, 0.f);
            if (grow < M) {
                v = *(const float4*)&Xp[(size_t)grow * K + kk + c];
                if (RELU) {
                    v.x = fmaxf(v.x, 0.f); v.y = fmaxf(v.y, 0.f);
                    v.z = fmaxf(v.z, 0.f); v.w = fmaxf(v.w, 0.f);
                }
            }
            *(float4*)&Xs[r * 68 + c] = v;
        }
        __syncthreads();

#pragma unroll
        for (int k = 0; k < 64; k++) {
            float4 b4 = *(float4*)&Ws[k * 64 + (tx << 2)];
            float a0 = Xs[(ty * 4 + 0) * 68 + k];
            float a1 = Xs[(ty * 4 + 1) * 68 + k];
            float a2 = Xs[(ty * 4 + 2) * 68 + k];
            float a3 = Xs[(ty * 4 + 3) * 68 + k];
            acc[0][0] += a0 * b4.x; acc[0][1] += a0 * b4.y; acc[0][2] += a0 * b4.z; acc[0][3] += a0 * b4.w;
            acc[1][0] += a1 * b4.x; acc[1][1] += a1 * b4.y; acc[1][2] += a1 * b4.z; acc[1][3] += a1 * b4.w;
            acc[2][0] += a2 * b4.x; acc[2][1] += a2 * b4.y; acc[2][2] += a2 * b4.z; acc[2][3] += a2 * b4.w;
            acc[3][0] += a3 * b4.x; acc[3][1] += a3 * b4.y; acc[3][2] += a3 * b4.z; acc[3][3] += a3 * b4.w;
        }
        __syncthreads();
    }

#pragma unroll
    for (int r = 0; r < 4; r++) {
        int grow = row0 + ty * 4 + r;
        if (grow < M) {
            *(float4*)&g_H[(size_t)grow * HID + (tx << 2)] =
                make_float4(acc[r][0], acc[r][1], acc[r][2], acc[r][3]);
        }
    }
}

// ---------------------------------------------------------------------------
// per-node: es = h.a_src, ed = h.a_dst, self-edge logit, init running max
// one warp per node; h = g_H
// ---------------------------------------------------------------------------
__global__ void __launch_bounds__(256)
node_prep(const float* __restrict__ as, const float* __restrict__ ad, int N) {
    int idx = blockIdx.x * blockDim.x + threadIdx.x;
    int node = idx >> 5;
    int lane = idx & 31;
    if (node >= N) return;
    const float* h = g_H + (size_t)node * HID;
    float h0 = h[lane], h1 = h[lane + 32];
    float es = h0 * as[lane] + h1 * as[lane + 32];
    float ed = h0 * ad[lane] + h1 * ad[lane + 32];
#pragma unroll
    for (int o = 16; o; o >>= 1) {
        es += __shfl_xor_sync(0xffffffffu, es, o);
        ed += __shfl_xor_sync(0xffffffffu, ed, o);
    }
    if (lane == 0) {
        g_es[node] = es;
        g_ed[node] = ed;
        float se = leaky(es + ed);       // self-loop edge logit
        g_selfe[node] = se;
        g_menc[node] = encf(se);         // max init includes self-loop
    }
}

// ---------------------------------------------------------------------------
// edge pass 1: e = leaky(es[src]+ed[dst]); store; atomicMax into m[dst]
// ---------------------------------------------------------------------------
__global__ void __launch_bounds__(256)
edge_max(int E) {
    int e = blockIdx.x * blockDim.x + threadIdx.x;
    if (e >= E) return;
    int s = g_src[e], d = g_dst[e];
    float v = leaky(g_es[s] + g_ed[d]);
    g_ew[e] = v;
    atomicMax(&g_menc[d], encf(v));
}

// ---------------------------------------------------------------------------
// per-node: decode max; init s with self-loop term
// ---------------------------------------------------------------------------
__global__ void __launch_bounds__(256)
node_m(int N) {
    int i = blockIdx.x * blockDim.x + threadIdx.x;
    if (i >= N) return;
    float m = decf(g_menc[i]);
    g_m[i] = m;
    g_s[i] = __expf(g_selfe[i] - m);
}

// ---------------------------------------------------------------------------
// edge pass 2: ex = exp(e - m[dst]); store; atomicAdd into s[dst]
// ---------------------------------------------------------------------------
__global__ void __launch_bounds__(256)
edge_exp(int E) {
    int e = blockIdx.x * blockDim.x + threadIdx.x;
    if (e >= E) return;
    int d = g_dst[e];
    float ex = __expf(g_ew[e] - g_m[d]);
    g_ew[e] = ex;
    atomicAdd(&g_s[d], ex);
}

// ---------------------------------------------------------------------------
// per-node: dst = alpha_self * h + b   (16 threads / node, float4 each)
// FINAL: write to `out` param, else to g_O
// ---------------------------------------------------------------------------
template<bool FINAL>
__global__ void __launch_bounds__(256)
node_init_out(const float* __restrict__ b, float* __restrict__ out, int N) {
    int t = blockIdx.x * blockDim.x + threadIdx.x;
    int i = t >> 4;
    if (i >= N) return;
    int q = (t & 15) << 2;
    float* dst = FINAL ? out : g_O;
    float w = __expf(g_selfe[i] - g_m[i]) / g_s[i];
    float4 h4 = *(const float4*)&g_H[(size_t)i * HID + q];
    float4 b4 = *(const float4*)&b[q];
    float4 o;
    o.x = w * h4.x + b4.x; o.y = w * h4.y + b4.y;
    o.z = w * h4.z + b4.z; o.w = w * h4.w + b4.w;
    *(float4*)&dst[(size_t)i * HID + q] = o;
}

// ---------------------------------------------------------------------------
// edge pass 3: dst[d] += (ex/s[d]) * g_H[src]
// 16 threads/edge: float4 gather + 4 scalar reds (REDG.ADD.F32)
// ---------------------------------------------------------------------------
template<bool FINAL>
__global__ void __launch_bounds__(256)
edge_scatter(float* __restrict__ out, int E) {
    int t = blockIdx.x * blockDim.x + threadIdx.x;
    int e = t >> 4;
    if (e >= E) return;
    int q = (t & 15) << 2;
    float* dst = FINAL ? out : g_O;
    int s = g_src[e], d = g_dst[e];
    float w = g_ew[e] / g_s[d];
    float4 v = *(const float4*)&g_H[(size_t)s * HID + q];
    float* o = &dst[(size_t)d * HID + q];
    atomicAdd(o + 0, w * v.x);
    atomicAdd(o + 1, w * v.y);
    atomicAdd(o + 2, w * v.z);
    atomicAdd(o + 3, w * v.w);
}

// ---------------------------------------------------------------------------
// host driver
// ---------------------------------------------------------------------------
template<bool FINAL>
static void run_layer_rest(const float* as, const float* ad, const float* b,
                           float* outp, int N, int E) {
    node_prep<<<(N * 32 + 255) / 256, 256>>>(as, ad, N);
    edge_max<<<(E + 255) / 256, 256>>>(E);
    node_m<<<(N + 255) / 256, 256>>>(N);
    edge_exp<<<(E + 255) / 256, 256>>>(E);
    node_init_out<FINAL><<<(N * 16 + 255) / 256, 256>>>(b, outp, N);
    edge_scatter<FINAL><<<(E * 16 + 255) / 256, 256>>>(outp, E);
}

extern "C" void kernel_launch(void* const* d_in, const int* in_sizes, int n_in,
                              void* d_out, int out_size) {
    const float* x   = (const float*)d_in[0];
    const void*  ei  = d_in[1];
    const float* W1  = (const float*)d_in[2];
    const float* as1 = (const float*)d_in[3];
    const float* ad1 = (const float*)d_in[4];
    const float* b1  = (const float*)d_in[5];
    const float* W2  = (const float*)d_in[6];
    const float* as2 = (const float*)d_in[7];
    const float* ad2 = (const float*)d_in[8];
    const float* b2  = (const float*)d_in[9];
    const float* W3  = (const float*)d_in[10];
    const float* as3 = (const float*)d_in[11];
    const float* ad3 = (const float*)d_in[12];
    const float* b3  = (const float*)d_in[13];

    int hid = in_sizes[3];            // 64
    int fin = in_sizes[2] / hid;      // 128
    int N   = in_sizes[0] / fin;
    int E   = in_sizes[1] / 2;
    float* out = (float*)d_out;

    // detect int32 vs int64 edge_index.
    // scan fits in the smaller (int32) interpretation: 4096 u64 = 8192 int32 <= 2E.
    int nscan = 4096;
    if (nscan > E / 2) nscan = E / 2 > 0 ? E / 2 : 1;
    detect_dtype<<<1, 256>>>((const unsigned long long*)ei, nscan);
    conv_idx<<<(E + 255) / 256, 256>>>(ei, E, N);

    int gblk = (N + 63) / 64;

    // layer 1: input = x (no relu)
    gemm_k<false, false><<<gblk, 256>>>(x, W1, N, fin);
    run_layer_rest<false>(as1, ad1, b1, nullptr, N, E);

    // layer 2: input = relu(g_O)
    gemm_k<true, true><<<gblk, 256>>>(nullptr, W2, N, hid);
    run_layer_rest<false>(as2, ad2, b2, nullptr, N, E);

    // layer 3: input = relu(g_O), output -> d_out
    gemm_k<true, true><<<gblk, 256>>>(nullptr, W3, N, hid);
    run_layer_rest<true>(as3, ad3, b3, out, N, E);
}

// round 8
// speedup vs baseline: 1.7198x; 1.7198x over previous
#include <cuda_runtime.h>
#include <cstdint>

// ---------------------------------------------------------------------------
// GAT (3 layers, single head) on GB300.
//  0: x [N, F_IN] f32
//  1: edge_index [2, E] int (dtype detected at runtime: int32 vs int64)
//  2..5:  W1 [F_IN,64], a_src1[64], a_dst1[64], b1[64]
//  6..9:  W2 [64,64],   a_src2,    a_dst2,    b2
// 10..13: W3 [64,64],   a_src3,    a_dst3,    b3
// output: [N, 64] f32
// ---------------------------------------------------------------------------

#define HID 64
#define NMAX 131072
#define EMAX 3400000

__device__ __align__(16) int      g_src[EMAX];
__device__ __align__(16) int      g_dst[EMAX];
__device__ __align__(16) float    g_ew[EMAX];                  // e, then exp(e-m)
__device__ __align__(16) float    g_H[(size_t)NMAX * HID];     // post-GEMM hidden
__device__ __align__(16) float    g_O[(size_t)NMAX * HID];     // aggregated output
__device__ __align__(16) float    g_es[NMAX];
__device__ __align__(16) float    g_ed[NMAX];
__device__ __align__(16) float    g_selfe[NMAX];
__device__ __align__(16) float    g_m[NMAX];
__device__ __align__(16) float    g_s[NMAX];
__device__ __align__(16) unsigned g_menc[NMAX];
__device__ int g_is32;

// monotone float<->uint encoding for atomicMax on floats (handles negatives)
__device__ __forceinline__ unsigned encf(float f) {
    unsigned u = __float_as_uint(f);
    return (u & 0x80000000u) ? ~u : (u | 0x80000000u);
}
__device__ __forceinline__ float decf(unsigned u) {
    return __uint_as_float((u & 0x80000000u) ? (u & 0x7fffffffu) : ~u);
}

__device__ __forceinline__ float leaky(float v) { return v > 0.f ? v : 0.2f * v; }

// vector reduction into global memory (sm_90+): 4x fewer LTS atomic ops
__device__ __forceinline__ void red_add_v4(float* p, float x, float y, float z, float w) {
    size_t gp = __cvta_generic_to_global(p);
    asm volatile("red.global.add.v4.f32 [%0], {%1,%2,%3,%4};"
                 :: "l"(gp), "f"(x), "f"(y), "f"(z), "f"(w) : "memory");
}

// ---------------------------------------------------------------------------
// dtype detection: if the buffer is really int64, every value < N (=1e5).
// If it's int32 read as int64, most words pack two ids -> value >= 2^32.
// ---------------------------------------------------------------------------
__global__ void detect_dtype(const unsigned long long* __restrict__ ei, int nscan) {
    __shared__ int flag;
    if (threadIdx.x == 0) flag = 0;
    __syncthreads();
    for (int j = threadIdx.x; j < nscan; j += blockDim.x)
        if (ei[j] >= 0x100000000ull) flag = 1;
    __syncthreads();
    if (threadIdx.x == 0) g_is32 = flag;
}

// ---------------------------------------------------------------------------
// edge index conversion (once, reused by all 3 layers); clamps to [0,N)
// ---------------------------------------------------------------------------
__global__ void conv_idx(const void* __restrict__ eiv, int E, int N) {
    int i = blockIdx.x * blockDim.x + threadIdx.x;
    if (i >= E) return;
    int s, d;
    if (g_is32) {
        const int* p = (const int*)eiv;
        s = p[i]; d = p[(size_t)E + i];
    } else {
        const long long* p = (const long long*)eiv;
        s = (int)p[i]; d = (int)p[(size_t)E + i];
    }
    s = min(max(s, 0), N - 1);
    d = min(max(d, 0), N - 1);
    g_src[i] = s;
    g_dst[i] = d;
}

// ---------------------------------------------------------------------------
// GEMM: g_H[M,64] = act(X[M,K]) @ W[K,64].  K in {64,128}.
// 64x64 block tile, 256 threads, 4x4 register tile per thread.
// Fused epilogue computes es = h.a_src, ed = h.a_dst, self-loop logit and
// initializes the running max — straight from the accumulators (no re-read).
// ---------------------------------------------------------------------------
template<bool RELU, bool FROM_GO>
__global__ void __launch_bounds__(256)
gemm_k(const float* __restrict__ X, const float* __restrict__ W,
       const float* __restrict__ as, const float* __restrict__ ad,
       int M, int K) {
    __shared__ float Ws[64 * 64];
    __shared__ float Xs[64 * 68];  // stride 68 to dodge bank conflicts

    const int tid = threadIdx.x;
    const int tx = tid & 15;        // 16 col-groups of 4 cols
    const int ty = tid >> 4;        // 16 row-groups of 4 rows
    const int row0 = blockIdx.x << 6;

    const float* __restrict__ Xp = FROM_GO ? g_O : X;

    float acc[4][4];
#pragma unroll
    for (int r = 0; r < 4; r++)
#pragma unroll
        for (int c = 0; c < 4; c++) acc[r][c] = 0.f;

    for (int kk = 0; kk < K; kk += 64) {
#pragma unroll
        for (int p = 0; p < 4; p++) {
            int r = ty + (p << 4);          // 0..63
            int c = tx << 2;                // 0..60
            *(float4*)&Ws[r * 64 + c] = *(const float4*)&W[(size_t)(kk + r) * HID + c];
            int grow = row0 + r;
            float4 v = make_float4(0.f, 0.f, 0.f, 0.f);
            if (grow < M) {
                v = *(const float4*)&Xp[(size_t)grow * K + kk + c];
                if (RELU) {
                    v.x = fmaxf(v.x, 0.f); v.y = fmaxf(v.y, 0.f);
                    v.z = fmaxf(v.z, 0.f); v.w = fmaxf(v.w, 0.f);
                }
            }
            *(float4*)&Xs[r * 68 + c] = v;
        }
        __syncthreads();

#pragma unroll
        for (int k = 0; k < 64; k++) {
            float4 b4 = *(float4*)&Ws[k * 64 + (tx << 2)];
            float a0 = Xs[(ty * 4 + 0) * 68 + k];
            float a1 = Xs[(ty * 4 + 1) * 68 + k];
            float a2 = Xs[(ty * 4 + 2) * 68 + k];
            float a3 = Xs[(ty * 4 + 3) * 68 + k];
            acc[0][0] += a0 * b4.x; acc[0][1] += a0 * b4.y; acc[0][2] += a0 * b4.z; acc[0][3] += a0 * b4.w;
            acc[1][0] += a1 * b4.x; acc[1][1] += a1 * b4.y; acc[1][2] += a1 * b4.z; acc[1][3] += a1 * b4.w;
            acc[2][0] += a2 * b4.x; acc[2][1] += a2 * b4.y; acc[2][2] += a2 * b4.z; acc[2][3] += a2 * b4.w;
            acc[3][0] += a3 * b4.x; acc[3][1] += a3 * b4.y; acc[3][2] += a3 * b4.z; acc[3][3] += a3 * b4.w;
        }
        __syncthreads();
    }

    // store H tile
#pragma unroll
    for (int r = 0; r < 4; r++) {
        int grow = row0 + ty * 4 + r;
        if (grow < M) {
            *(float4*)&g_H[(size_t)grow * HID + (tx << 2)] =
                make_float4(acc[r][0], acc[r][1], acc[r][2], acc[r][3]);
        }
    }

    // fused attention-logit epilogue: per-row dot with a_src/a_dst, reduced
    // over the 16 tx lanes (shfl_xor < 16 stays within the 16-lane group).
    float4 as4 = *(const float4*)&as[tx << 2];
    float4 ad4 = *(const float4*)&ad[tx << 2];
    float pes[4], ped[4];
#pragma unroll
    for (int r = 0; r < 4; r++) {
        pes[r] = acc[r][0] * as4.x + acc[r][1] * as4.y + acc[r][2] * as4.z + acc[r][3] * as4.w;
        ped[r] = acc[r][0] * ad4.x + acc[r][1] * ad4.y + acc[r][2] * ad4.z + acc[r][3] * ad4.w;
    }
#pragma unroll
    for (int o = 8; o; o >>= 1) {
#pragma unroll
        for (int r = 0; r < 4; r++) {
            pes[r] += __shfl_xor_sync(0xffffffffu, pes[r], o);
            ped[r] += __shfl_xor_sync(0xffffffffu, ped[r], o);
        }
    }
    if (tx == 0) {
#pragma unroll
        for (int r = 0; r < 4; r++) {
            int grow = row0 + ty * 4 + r;
            if (grow < M) {
                float es = pes[r], ed = ped[r];
                g_es[grow] = es;
                g_ed[grow] = ed;
                float se = leaky(es + ed);      // self-loop logit
                g_selfe[grow] = se;
                g_menc[grow] = encf(se);        // running max init incl. self-loop
            }
        }
    }
}

// ---------------------------------------------------------------------------
// edge pass 1: e = leaky(es[src]+ed[dst]); store; atomicMax into m[dst]
// ---------------------------------------------------------------------------
__global__ void __launch_bounds__(256)
edge_max(int E) {
    int e = blockIdx.x * blockDim.x + threadIdx.x;
    if (e >= E) return;
    int s = g_src[e], d = g_dst[e];
    float v = leaky(g_es[s] + g_ed[d]);
    g_ew[e] = v;
    atomicMax(&g_menc[d], encf(v));
}

// ---------------------------------------------------------------------------
// per-node: decode max; init s with self-loop term
// ---------------------------------------------------------------------------
__global__ void __launch_bounds__(256)
node_m(int N) {
    int i = blockIdx.x * blockDim.x + threadIdx.x;
    if (i >= N) return;
    float m = decf(g_menc[i]);
    g_m[i] = m;
    g_s[i] = __expf(g_selfe[i] - m);
}

// ---------------------------------------------------------------------------
// edge pass 2: ex = exp(e - m[dst]); store; atomicAdd into s[dst]
// ---------------------------------------------------------------------------
__global__ void __launch_bounds__(256)
edge_exp(int E) {
    int e = blockIdx.x * blockDim.x + threadIdx.x;
    if (e >= E) return;
    int d = g_dst[e];
    float ex = __expf(g_ew[e] - g_m[d]);
    g_ew[e] = ex;
    atomicAdd(&g_s[d], ex);
}

// ---------------------------------------------------------------------------
// per-node: dst = alpha_self * h + b   (16 threads / node, float4 each)
// ---------------------------------------------------------------------------
template<bool FINAL>
__global__ void __launch_bounds__(256)
node_init_out(const float* __restrict__ b, float* __restrict__ out, int N) {
    int t = blockIdx.x * blockDim.x + threadIdx.x;
    int i = t >> 4;
    if (i >= N) return;
    int q = (t & 15) << 2;
    float* dst = FINAL ? out : g_O;
    float w = __expf(g_selfe[i] - g_m[i]) / g_s[i];
    float4 h4 = *(const float4*)&g_H[(size_t)i * HID + q];
    float4 b4 = *(const float4*)&b[q];
    float4 o;
    o.x = w * h4.x + b4.x; o.y = w * h4.y + b4.y;
    o.z = w * h4.z + b4.z; o.w = w * h4.w + b4.w;
    *(float4*)&dst[(size_t)i * HID + q] = o;
}

// ---------------------------------------------------------------------------
// edge pass 3: dst[d] += (ex/s[d]) * g_H[src]
// 16 threads/edge: float4 gather + one v4 red (4x fewer LTS atomic ops)
// ---------------------------------------------------------------------------
template<bool FINAL>
__global__ void __launch_bounds__(256)
edge_scatter(float* __restrict__ out, int E) {
    int t = blockIdx.x * blockDim.x + threadIdx.x;
    int e = t >> 4;
    if (e >= E) return;
    int q = (t & 15) << 2;
    float* dst = FINAL ? out : g_O;
    int s = g_src[e], d = g_dst[e];
    float w = g_ew[e] / g_s[d];
    float4 v = *(const float4*)&g_H[(size_t)s * HID + q];
    red_add_v4(&dst[(size_t)d * HID + q], w * v.x, w * v.y, w * v.z, w * v.w);
}

// ---------------------------------------------------------------------------
// host driver
// ---------------------------------------------------------------------------
template<bool FINAL>
static void run_layer_rest(const float* b, float* outp, int N, int E) {
    edge_max<<<(E + 255) / 256, 256>>>(E);
    node_m<<<(N + 255) / 256, 256>>>(N);
    edge_exp<<<(E + 255) / 256, 256>>>(E);
    node_init_out<FINAL><<<(N * 16 + 255) / 256, 256>>>(b, outp, N);
    edge_scatter<FINAL><<<(E * 16 + 255) / 256, 256>>>(outp, E);
}

extern "C" void kernel_launch(void* const* d_in, const int* in_sizes, int n_in,
                              void* d_out, int out_size) {
    const float* x   = (const float*)d_in[0];
    const void*  ei  = d_in[1];
    const float* W1  = (const float*)d_in[2];
    const float* as1 = (const float*)d_in[3];
    const float* ad1 = (const float*)d_in[4];
    const float* b1  = (const float*)d_in[5];
    const float* W2  = (const float*)d_in[6];
    const float* as2 = (const float*)d_in[7];
    const float* ad2 = (const float*)d_in[8];
    const float* b2  = (const float*)d_in[9];
    const float* W3  = (const float*)d_in[10];
    const float* as3 = (const float*)d_in[11];
    const float* ad3 = (const float*)d_in[12];
    const float* b3  = (const float*)d_in[13];

    int hid = in_sizes[3];            // 64
    int fin = in_sizes[2] / hid;      // 128
    int N   = in_sizes[0] / fin;
    int E   = in_sizes[1] / 2;
    float* out = (float*)d_out;

    int nscan = 4096;
    if (nscan > E / 2) nscan = E / 2 > 0 ? E / 2 : 1;
    detect_dtype<<<1, 256>>>((const unsigned long long*)ei, nscan);
    conv_idx<<<(E + 255) / 256, 256>>>(ei, E, N);

    int gblk = (N + 63) / 64;

    // layer 1: input = x (no relu)
    gemm_k<false, false><<<gblk, 256>>>(x, W1, as1, ad1, N, fin);
    run_layer_rest<false>(b1, nullptr, N, E);

    // layer 2: input = relu(g_O)
    gemm_k<true, true><<<gblk, 256>>>(nullptr, W2, as2, ad2, N, hid);
    run_layer_rest<false>(b2, nullptr, N, E);

    // layer 3: input = relu(g_O), output -> d_out
    gemm_k<true, true><<<gblk, 256>>>(nullptr, W3, as3, ad3, N, hid);
    run_layer_rest<true>(b3, out, N, E);
}

// round 9
// speedup vs baseline: 4.0745x; 2.3692x over previous
#include <cuda_runtime.h>
#include <cstdint>

// ---------------------------------------------------------------------------
// GAT (3 layers, single head) on GB300 — CSR edition.
//  0: x [N, F_IN] f32
//  1: edge_index [2, E] (runtime-detected int32 vs int64)
//  2..5:  W1 [F_IN,64], a_src1[64], a_dst1[64], b1[64]
//  6..9:  W2, as2, ad2, b2     10..13: W3, as3, ad3, b3
// output: [N, 64] f32
// ---------------------------------------------------------------------------

#define HID 64
#define NMAX 131072
#define EMAX 3400000
#define SCAN_B 512

__device__ __align__(16) int      g_src[EMAX];
__device__ __align__(16) int      g_dst[EMAX];
__device__ __align__(16) int      g_csrc[EMAX];     // CSR: src ids grouped by dst
__device__ __align__(16) float    g_ew[EMAX];       // per-CSR-slot e, then exp(e-m)
__device__ __align__(16) int      g_cnt[NMAX];      // histogram, then fill cursor
__device__ __align__(16) int      g_off[NMAX + 1];  // CSR row offsets
__device__ __align__(16) int      g_bsum[1024];
__device__ __align__(16) float    g_H[(size_t)NMAX * HID];   // post-GEMM hidden
__device__ __align__(16) float    g_O[(size_t)NMAX * HID];   // aggregated output
__device__ __align__(16) float    g_es[NMAX];
__device__ __align__(16) float    g_ed[NMAX];
__device__ __align__(16) float    g_selfe[NMAX];
__device__ int g_is32;

__device__ __forceinline__ float leaky(float v) { return v > 0.f ? v : 0.2f * v; }

// ---------------------------------------------------------------------------
// dtype detection: int32 buffer read as u64 packs two ids -> values >= 2^32
// ---------------------------------------------------------------------------
__global__ void detect_dtype(const unsigned long long* __restrict__ ei, int nscan) {
    __shared__ int flag;
    if (threadIdx.x == 0) flag = 0;
    __syncthreads();
    for (int j = threadIdx.x; j < nscan; j += blockDim.x)
        if (ei[j] >= 0x100000000ull) flag = 1;
    __syncthreads();
    if (threadIdx.x == 0) g_is32 = flag;
}

__global__ void conv_idx(const void* __restrict__ eiv, int E, int N) {
    int i = blockIdx.x * blockDim.x + threadIdx.x;
    if (i >= E) return;
    int s, d;
    if (g_is32) {
        const int* p = (const int*)eiv;
        s = p[i]; d = p[(size_t)E + i];
    } else {
        const long long* p = (const long long*)eiv;
        s = (int)p[i]; d = (int)p[(size_t)E + i];
    }
    s = min(max(s, 0), N - 1);
    d = min(max(d, 0), N - 1);
    g_src[i] = s;
    g_dst[i] = d;
}

// ---------------------------------------------------------------------------
// CSR build: zero hist -> histogram -> block scans -> scan of block sums ->
// add offsets -> copy cursors -> fill
// ---------------------------------------------------------------------------
__global__ void zero_cnt(int N) {
    int i = blockIdx.x * blockDim.x + threadIdx.x;
    if (i < N) g_cnt[i] = 0;
}
__global__ void hist_k(int E) {
    int i = blockIdx.x * blockDim.x + threadIdx.x;
    if (i < E) atomicAdd(&g_cnt[g_dst[i]], 1);
}
// per-block inclusive scan of g_cnt chunks -> g_off[i+1]; block totals -> g_bsum
__global__ void __launch_bounds__(SCAN_B) scan_block(int N) {
    __shared__ int ws[SCAN_B / 32];
    int tid = threadIdx.x;
    int gi = blockIdx.x * SCAN_B + tid;
    int v = (gi < N) ? g_cnt[gi] : 0;
    int lane = tid & 31, wid = tid >> 5;
    int x = v;
#pragma unroll
    for (int o = 1; o < 32; o <<= 1) {
        int y = __shfl_up_sync(0xffffffffu, x, o);
        if (lane >= o) x += y;
    }
    if (lane == 31) ws[wid] = x;
    __syncthreads();
    if (wid == 0) {
        int t = (lane < SCAN_B / 32) ? ws[lane] : 0;
#pragma unroll
        for (int o = 1; o < SCAN_B / 32; o <<= 1) {
            int y = __shfl_up_sync(0xffffffffu, t, o);
            if (lane >= o) t += y;
        }
        if (lane < SCAN_B / 32) ws[lane] = t;
    }
    __syncthreads();
    int incl = x + (wid > 0 ? ws[wid - 1] : 0);
    if (gi < N) g_off[gi + 1] = incl;
    if (tid == SCAN_B - 1) g_bsum[blockIdx.x] = incl;
}
// exclusive scan of block sums (nb <= 512), single block
__global__ void __launch_bounds__(SCAN_B) scan_bsums(int nb) {
    __shared__ int ws[SCAN_B / 32];
    int tid = threadIdx.x;
    int v = (tid < nb) ? g_bsum[tid] : 0;
    int lane = tid & 31, wid = tid >> 5;
    int x = v;
#pragma unroll
    for (int o = 1; o < 32; o <<= 1) {
        int y = __shfl_up_sync(0xffffffffu, x, o);
        if (lane >= o) x += y;
    }
    if (lane == 31) ws[wid] = x;
    __syncthreads();
    if (wid == 0) {
        int t = (lane < SCAN_B / 32) ? ws[lane] : 0;
#pragma unroll
        for (int o = 1; o < SCAN_B / 32; o <<= 1) {
            int y = __shfl_up_sync(0xffffffffu, t, o);
            if (lane >= o) t += y;
        }
        if (lane < SCAN_B / 32) ws[lane] = t;
    }
    __syncthreads();
    int incl = x + (wid > 0 ? ws[wid - 1] : 0);
    if (tid < nb) g_bsum[tid] = incl - v;   // exclusive
}
__global__ void add_offsets(int N) {
    int gi = blockIdx.x * blockDim.x + threadIdx.x;
    if (gi == 0) g_off[0] = 0;
    if (gi < N) g_off[gi + 1] += g_bsum[gi / SCAN_B];
}
__global__ void copy_cursor(int N) {
    int i = blockIdx.x * blockDim.x + threadIdx.x;
    if (i < N) g_cnt[i] = g_off[i];
}
__global__ void fill_csr(int E) {
    int i = blockIdx.x * blockDim.x + threadIdx.x;
    if (i >= E) return;
    int d = g_dst[i];
    int pos = atomicAdd(&g_cnt[d], 1);
    g_csrc[pos] = g_src[i];
}

// ---------------------------------------------------------------------------
// GEMM: g_H[M,64] = act(X[M,K]) @ W[K,64] with fused es/ed/selfe epilogue
// ---------------------------------------------------------------------------
template<bool RELU, bool FROM_GO>
__global__ void __launch_bounds__(256)
gemm_k(const float* __restrict__ X, const float* __restrict__ W,
       const float* __restrict__ as, const float* __restrict__ ad,
       int M, int K) {
    __shared__ float Ws[64 * 64];
    __shared__ float Xs[64 * 68];

    const int tid = threadIdx.x;
    const int tx = tid & 15;
    const int ty = tid >> 4;
    const int row0 = blockIdx.x << 6;

    const float* __restrict__ Xp = FROM_GO ? g_O : X;

    float acc[4][4];
#pragma unroll
    for (int r = 0; r < 4; r++)
#pragma unroll
        for (int c = 0; c < 4; c++) acc[r][c] = 0.f;

    for (int kk = 0; kk < K; kk += 64) {
#pragma unroll
        for (int p = 0; p < 4; p++) {
            int r = ty + (p << 4);
            int c = tx << 2;
            *(float4*)&Ws[r * 64 + c] = *(const float4*)&W[(size_t)(kk + r) * HID + c];
            int grow = row0 + r;
            float4 v = make_float4(0.f, 0.f, 0.f, 0.f);
            if (grow < M) {
                v = *(const float4*)&Xp[(size_t)grow * K + kk + c];
                if (RELU) {
                    v.x = fmaxf(v.x, 0.f); v.y = fmaxf(v.y, 0.f);
                    v.z = fmaxf(v.z, 0.f); v.w = fmaxf(v.w, 0.f);
                }
            }
            *(float4*)&Xs[r * 68 + c] = v;
        }
        __syncthreads();

#pragma unroll
        for (int k = 0; k < 64; k++) {
            float4 b4 = *(float4*)&Ws[k * 64 + (tx << 2)];
            float a0 = Xs[(ty * 4 + 0) * 68 + k];
            float a1 = Xs[(ty * 4 + 1) * 68 + k];
            float a2 = Xs[(ty * 4 + 2) * 68 + k];
            float a3 = Xs[(ty * 4 + 3) * 68 + k];
            acc[0][0] += a0 * b4.x; acc[0][1] += a0 * b4.y; acc[0][2] += a0 * b4.z; acc[0][3] += a0 * b4.w;
            acc[1][0] += a1 * b4.x; acc[1][1] += a1 * b4.y; acc[1][2] += a1 * b4.z; acc[1][3] += a1 * b4.w;
            acc[2][0] += a2 * b4.x; acc[2][1] += a2 * b4.y; acc[2][2] += a2 * b4.z; acc[2][3] += a2 * b4.w;
            acc[3][0] += a3 * b4.x; acc[3][1] += a3 * b4.y; acc[3][2] += a3 * b4.z; acc[3][3] += a3 * b4.w;
        }
        __syncthreads();
    }

#pragma unroll
    for (int r = 0; r < 4; r++) {
        int grow = row0 + ty * 4 + r;
        if (grow < M) {
            *(float4*)&g_H[(size_t)grow * HID + (tx << 2)] =
                make_float4(acc[r][0], acc[r][1], acc[r][2], acc[r][3]);
        }
    }

    float4 as4 = *(const float4*)&as[tx << 2];
    float4 ad4 = *(const float4*)&ad[tx << 2];
    float pes[4], ped[4];
#pragma unroll
    for (int r = 0; r < 4; r++) {
        pes[r] = acc[r][0] * as4.x + acc[r][1] * as4.y + acc[r][2] * as4.z + acc[r][3] * as4.w;
        ped[r] = acc[r][0] * ad4.x + acc[r][1] * ad4.y + acc[r][2] * ad4.z + acc[r][3] * ad4.w;
    }
#pragma unroll
    for (int o = 8; o; o >>= 1) {
#pragma unroll
        for (int r = 0; r < 4; r++) {
            pes[r] += __shfl_xor_sync(0xffffffffu, pes[r], o);
            ped[r] += __shfl_xor_sync(0xffffffffu, ped[r], o);
        }
    }
    if (tx == 0) {
#pragma unroll
        for (int r = 0; r < 4; r++) {
            int grow = row0 + ty * 4 + r;
            if (grow < M) {
                float es = pes[r], ed = ped[r];
                g_es[grow] = es;
                g_ed[grow] = ed;
                g_selfe[grow] = leaky(es + ed);
            }
        }
    }
}

// ---------------------------------------------------------------------------
// Fused softmax + aggregate: one warp per dst node, zero atomics.
// Pass A: e_i = leaky(es[src]+ed[dst]) -> g_ew, register max.
// Pass B: ex = exp(e-m) -> g_ew, register sum s.
// Pass C: acc = sum(ex_i * h[src_i]) + ex_self*h[node]; out = acc/s + b.
// ---------------------------------------------------------------------------
template<bool FINAL>
__global__ void __launch_bounds__(256)
agg_k(const float* __restrict__ b, float* __restrict__ out, int N) {
    int node = (blockIdx.x * 256 + threadIdx.x) >> 5;
    int lane = threadIdx.x & 31;
    if (node >= N) return;

    int beg = g_off[node], end = g_off[node + 1];
    float edn = g_ed[node];
    float selfe = g_selfe[node];

    // pass A: logits + max
    float m = selfe;
    for (int i = beg + lane; i < end; i += 32) {
        int s = g_csrc[i];
        float e = leaky(g_es[s] + edn);
        g_ew[i] = e;
        m = fmaxf(m, e);
    }
#pragma unroll
    for (int o = 16; o; o >>= 1) m = fmaxf(m, __shfl_xor_sync(0xffffffffu, m, o));

    // pass B: exp + sum
    float wself = __expf(selfe - m);
    float ssum = (lane == 0) ? wself : 0.f;
    for (int i = beg + lane; i < end; i += 32) {
        float ex = __expf(g_ew[i] - m);
        g_ew[i] = ex;
        ssum += ex;
    }
#pragma unroll
    for (int o = 16; o; o >>= 1) ssum += __shfl_xor_sync(0xffffffffu, ssum, o);

    // pass C: weighted feature gather, 2 edges/iter (16 lanes x float4 each)
    int half = lane >> 4;
    int q = (lane & 15) << 2;
    float4 acc = make_float4(0.f, 0.f, 0.f, 0.f);
    if (half == 0) {
        float4 hv = *(const float4*)&g_H[(size_t)node * HID + q];
        acc.x = wself * hv.x; acc.y = wself * hv.y;
        acc.z = wself * hv.z; acc.w = wself * hv.w;
    }
    for (int i = beg + half; i < end; i += 2) {
        int s = g_csrc[i];
        float wt = g_ew[i];
        float4 v = *(const float4*)&g_H[(size_t)s * HID + q];
        acc.x += wt * v.x; acc.y += wt * v.y;
        acc.z += wt * v.z; acc.w += wt * v.w;
    }
    acc.x += __shfl_xor_sync(0xffffffffu, acc.x, 16);
    acc.y += __shfl_xor_sync(0xffffffffu, acc.y, 16);
    acc.z += __shfl_xor_sync(0xffffffffu, acc.z, 16);
    acc.w += __shfl_xor_sync(0xffffffffu, acc.w, 16);

    if (half == 0) {
        float inv = 1.f / ssum;
        float4 b4 = *(const float4*)&b[q];
        float* dst = FINAL ? out : g_O;
        *(float4*)&dst[(size_t)node * HID + q] =
            make_float4(acc.x * inv + b4.x, acc.y * inv + b4.y,
                        acc.z * inv + b4.z, acc.w * inv + b4.w);
    }
}

// ---------------------------------------------------------------------------
// host driver
// ---------------------------------------------------------------------------
extern "C" void kernel_launch(void* const* d_in, const int* in_sizes, int n_in,
                              void* d_out, int out_size) {
    const float* x   = (const float*)d_in[0];
    const void*  ei  = d_in[1];
    const float* W1  = (const float*)d_in[2];
    const float* as1 = (const float*)d_in[3];
    const float* ad1 = (const float*)d_in[4];
    const float* b1  = (const float*)d_in[5];
    const float* W2  = (const float*)d_in[6];
    const float* as2 = (const float*)d_in[7];
    const float* ad2 = (const float*)d_in[8];
    const float* b2  = (const float*)d_in[9];
    const float* W3  = (const float*)d_in[10];
    const float* as3 = (const float*)d_in[11];
    const float* ad3 = (const float*)d_in[12];
    const float* b3  = (const float*)d_in[13];

    int hid = in_sizes[3];            // 64
    int fin = in_sizes[2] / hid;      // 128
    int N   = in_sizes[0] / fin;
    int E   = in_sizes[1] / 2;
    float* out = (float*)d_out;

    // edge index dtype detect + convert
    int nscan = 4096;
    if (nscan > E / 2) nscan = E / 2 > 0 ? E / 2 : 1;
    detect_dtype<<<1, 256>>>((const unsigned long long*)ei, nscan);
    conv_idx<<<(E + 255) / 256, 256>>>(ei, E, N);

    // CSR build (once, reused by 3 layers)
    int nb = (N + SCAN_B - 1) / SCAN_B;
    zero_cnt<<<(N + 255) / 256, 256>>>(N);
    hist_k<<<(E + 255) / 256, 256>>>(E);
    scan_block<<<nb, SCAN_B>>>(N);
    scan_bsums<<<1, SCAN_B>>>(nb);
    add_offsets<<<(N + 255) / 256, 256>>>(N);
    copy_cursor<<<(N + 255) / 256, 256>>>(N);
    fill_csr<<<(E + 255) / 256, 256>>>(E);

    int gblk = (N + 63) / 64;
    int ablk = (N * 32 + 255) / 256;

    // layer 1
    gemm_k<false, false><<<gblk, 256>>>(x, W1, as1, ad1, N, fin);
    agg_k<false><<<ablk, 256>>>(b1, nullptr, N);
    // layer 2
    gemm_k<true, true><<<gblk, 256>>>(nullptr, W2, as2, ad2, N, hid);
    agg_k<false><<<ablk, 256>>>(b2, nullptr, N);
    // layer 3
    gemm_k<true, true><<<gblk, 256>>>(nullptr, W3, as3, ad3, N, hid);
    agg_k<true><<<ablk, 256>>>(b3, out, N);
}